// round 2
// baseline (speedup 1.0000x reference)
#include <cuda_runtime.h>

// LightGCN 3-layer propagation on GB300 (sm_103a).
// Pipeline:
//   deg  = bincount(row)                  (atomic float adds)
//   dinv = deg>0 ? rsqrt(deg) : 0
//   norm = dinv[row]*dinv[col]
//   h0   = concat(user_emb, item_emb); acc = h0
//   3x:  h_{k+1}[r] += norm[e]*h_k[c]     (gather + red.global.add.v4.f32 scatter)
//        acc += h_{k+1};  zero the ping-pong buffer for the next layer
//   out  = acc / 4  (folded into last accumulate)

#define NU 200000
#define NI 100000
#define NN 300000
#define DIM 64
#define NE 1200000
#define NF4 (NN * (DIM / 4))   // 4.8M float4 per node buffer

// Scratch (static __device__ globals — no runtime allocation allowed)
__device__ float g_dinv[NN];
__device__ float g_norm[NE];
__device__ float g_hA[(size_t)NN * DIM];
__device__ float g_hB[(size_t)NN * DIM];

__global__ void k_zero_dinv() {
    int i = blockIdx.x * blockDim.x + threadIdx.x;
    if (i < NN) g_dinv[i] = 0.0f;
}

__global__ void k_deg(const int* __restrict__ row) {
    int e = blockIdx.x * blockDim.x + threadIdx.x;
    if (e < NE) atomicAdd(&g_dinv[row[e]], 1.0f);
}

__global__ void k_dinv() {
    int i = blockIdx.x * blockDim.x + threadIdx.x;
    if (i < NN) {
        float d = g_dinv[i];
        g_dinv[i] = (d > 0.0f) ? rsqrtf(d) : 0.0f;
    }
}

__global__ void k_norm(const int* __restrict__ row, const int* __restrict__ col) {
    int e = blockIdx.x * blockDim.x + threadIdx.x;
    if (e < NE) g_norm[e] = __ldg(&g_dinv[row[e]]) * __ldg(&g_dinv[col[e]]);
}

// Initialize h (layer-0 embedding), acc (= out buffer), and zero hB (layer-0 dest).
__global__ void k_init(const float4* __restrict__ ue, const float4* __restrict__ ie,
                       float4* __restrict__ out) {
    int i = blockIdx.x * blockDim.x + threadIdx.x;
    if (i < NF4) {
        float4 v = (i < NU * (DIM / 4)) ? __ldg(&ue[i]) : __ldg(&ie[i - NU * (DIM / 4)]);
        out[i] = v;
        reinterpret_cast<float4*>(g_hA)[i] = v;
        reinterpret_cast<float4*>(g_hB)[i] = make_float4(0.f, 0.f, 0.f, 0.f);
    }
}

// One edge handled by 16 lanes (each: one float4 gather + one red.v4 scatter).
__global__ void k_scatter(int srcIsA, const int* __restrict__ row,
                          const int* __restrict__ col) {
    int t = blockIdx.x * blockDim.x + threadIdx.x;
    int e = t >> 4;
    if (e >= NE) return;
    int li = t & 15;

    const float* __restrict__ src = srcIsA ? g_hA : g_hB;
    float* __restrict__ dst       = srcIsA ? g_hB : g_hA;

    int c    = __ldg(&col[e]);
    int r    = __ldg(&row[e]);
    float nm = __ldg(&g_norm[e]);

    float4 v = *reinterpret_cast<const float4*>(src + (size_t)c * DIM + li * 4);
    float* p = dst + (size_t)r * DIM + li * 4;
    asm volatile("red.global.add.v4.f32 [%0], {%1, %2, %3, %4};"
                 :: "l"(p), "f"(v.x * nm), "f"(v.y * nm), "f"(v.z * nm), "f"(v.w * nm)
                 : "memory");
}

// acc += h; zero the other buffer (next layer's scatter destination).
// finalScale: apply the /(N_LAYERS+1) = 0.25 on the last accumulate, skip zeroing.
__global__ void k_acc(float4* __restrict__ out, int hIsB, int finalScale) {
    int i = blockIdx.x * blockDim.x + threadIdx.x;
    if (i >= NF4) return;
    float4* __restrict__ h = hIsB ? reinterpret_cast<float4*>(g_hB)
                                  : reinterpret_cast<float4*>(g_hA);
    float4 a = out[i];
    float4 b = h[i];
    a.x += b.x; a.y += b.y; a.z += b.z; a.w += b.w;
    if (finalScale) {
        a.x *= 0.25f; a.y *= 0.25f; a.z *= 0.25f; a.w *= 0.25f;
    } else {
        float4* __restrict__ z = hIsB ? reinterpret_cast<float4*>(g_hA)
                                      : reinterpret_cast<float4*>(g_hB);
        z[i] = make_float4(0.f, 0.f, 0.f, 0.f);
    }
    out[i] = a;
}

extern "C" void kernel_launch(void* const* d_in, const int* in_sizes, int n_in,
                              void* d_out, int out_size) {
    const float* ue = (const float*)d_in[0];   // user_emb  [NU, 64]
    const float* ie = (const float*)d_in[1];   // item_emb  [NI, 64]
    const int*   ei = (const int*)d_in[2];     // edge_index [2, NE]
    const int* row = ei;
    const int* col = ei + NE;
    float4* out = (float4*)d_out;

    const int B = 256;
    const int gN  = (NN + B - 1) / B;
    const int gE  = (NE + B - 1) / B;
    const int gF4 = (NF4 + B - 1) / B;
    const int gSc = ((NE * 16) + B - 1) / B;

    // Norm precompute
    k_zero_dinv<<<gN, B>>>();
    k_deg<<<gE, B>>>(row);
    k_dinv<<<gN, B>>>();
    k_norm<<<gE, B>>>(row, col);

    // h0 and acc init (also zeroes hB)
    k_init<<<gF4, B>>>((const float4*)ue, (const float4*)ie, out);

    // Layer 1: A -> B
    k_scatter<<<gSc, B>>>(1, row, col);
    k_acc<<<gF4, B>>>(out, 1, 0);       // acc += hB; zero hA
    // Layer 2: B -> A
    k_scatter<<<gSc, B>>>(0, row, col);
    k_acc<<<gF4, B>>>(out, 0, 0);       // acc += hA; zero hB
    // Layer 3: A -> B
    k_scatter<<<gSc, B>>>(1, row, col);
    k_acc<<<gF4, B>>>(out, 1, 1);       // acc = (acc + hB) * 0.25
}

// round 3
// speedup vs baseline: 1.4518x; 1.4518x over previous
#include <cuda_runtime.h>

// LightGCN 3-layer propagation on GB300 (sm_103a) — CSR gather formulation.
// h_{k+1}[r] = sum_{e: row[e]=r} norm[e]*h_k[col[e]]  in registers (no atomics),
// fused with out accumulation. Layer 1 reads embeddings directly; layer 3
// skips the h write and folds the final /4.

#define NU 200000
#define NI 100000
#define NN 300000
#define DIM 64
#define NE 1200000
#define NBLK ((NN + 1023) / 1024)   // 293 scan blocks

__device__ int   g_cnt[NN];
__device__ int   g_offs[NN];
__device__ int   g_cur[NN];
__device__ int   g_bsum[NBLK];
__device__ int   g_boff[NBLK];
__device__ float g_dinv[NN];
__device__ int   g_colS[NE];
__device__ float g_normS[NE];
__device__ float g_hA[(size_t)NN * DIM];
__device__ float g_hB[(size_t)NN * DIM];

__global__ void k_zero_cnt() {
    int i = blockIdx.x * blockDim.x + threadIdx.x;
    if (i < NN) g_cnt[i] = 0;
}

__global__ void k_count(const int* __restrict__ row) {
    int e = blockIdx.x * blockDim.x + threadIdx.x;
    if (e < NE) atomicAdd(&g_cnt[row[e]], 1);
}

__global__ void k_dinv() {
    int i = blockIdx.x * blockDim.x + threadIdx.x;
    if (i < NN) {
        int d = g_cnt[i];
        g_dinv[i] = (d > 0) ? rsqrtf((float)d) : 0.0f;
    }
}

__global__ void k_scan1() {
    __shared__ int sh[1024];
    int i = blockIdx.x * 1024 + threadIdx.x;
    int v = (i < NN) ? g_cnt[i] : 0;
    sh[threadIdx.x] = v;
    __syncthreads();
    for (int off = 1; off < 1024; off <<= 1) {
        int t = (threadIdx.x >= off) ? sh[threadIdx.x - off] : 0;
        __syncthreads();
        sh[threadIdx.x] += t;
        __syncthreads();
    }
    if (i < NN) g_offs[i] = sh[threadIdx.x] - v;
    if (threadIdx.x == 1023) g_bsum[blockIdx.x] = sh[1023];
}

__global__ void k_scan2() {
    __shared__ int sh[512];
    int i = threadIdx.x;
    int v = (i < NBLK) ? g_bsum[i] : 0;
    sh[i] = v;
    __syncthreads();
    for (int off = 1; off < 512; off <<= 1) {
        int t = (i >= off) ? sh[i - off] : 0;
        __syncthreads();
        sh[i] += t;
        __syncthreads();
    }
    if (i < NBLK) g_boff[i] = sh[i] - v;
}

__global__ void k_scan3() {
    int i = blockIdx.x * blockDim.x + threadIdx.x;
    if (i < NN) {
        int o = g_offs[i] + g_boff[i >> 10];
        g_offs[i] = o;
        g_cur[i]  = o;
    }
}

__global__ void k_fill(const int* __restrict__ row, const int* __restrict__ col) {
    int e = blockIdx.x * blockDim.x + threadIdx.x;
    if (e < NE) {
        int r = row[e], c = col[e];
        int pos = atomicAdd(&g_cur[r], 1);
        g_colS[pos]  = c;
        g_normS[pos] = __ldg(&g_dinv[r]) * __ldg(&g_dinv[c]);
    }
}

// mode: 0 = layer1 (src = embeddings, dst = hA, out = x + h)
//       1 = layer2 (src = hA, dst = hB, out += h)
//       2 = layer3 (src = hB, no dst, out = (out + h)*0.25)
__global__ void __launch_bounds__(256) k_layer(
    const float4* __restrict__ ue, const float4* __restrict__ ie,
    float4* __restrict__ out, int mode)
{
    int t = blockIdx.x * blockDim.x + threadIdx.x;
    int r = t >> 4;
    if (r >= NN) return;
    int li = t & 15;

    const float4* __restrict__ src =
        (mode == 1) ? (const float4*)g_hA :
        (mode == 2) ? (const float4*)g_hB : nullptr;
    float4* __restrict__ dsth =
        (mode == 0) ? (float4*)g_hA :
        (mode == 1) ? (float4*)g_hB : nullptr;

    int start = g_offs[r];
    int cnt   = g_cnt[r];

    float4 acc = make_float4(0.f, 0.f, 0.f, 0.f);
    for (int j = 0; j < cnt; j++) {
        int   c  = __ldg(&g_colS[start + j]);
        float nm = __ldg(&g_normS[start + j]);
        float4 v;
        if (mode == 0)
            v = (c < NU) ? __ldg(&ue[(size_t)c * 16 + li])
                         : __ldg(&ie[(size_t)(c - NU) * 16 + li]);
        else
            v = __ldg(&src[(size_t)c * 16 + li]);
        acc.x += nm * v.x; acc.y += nm * v.y;
        acc.z += nm * v.z; acc.w += nm * v.w;
    }

    size_t oi = (size_t)r * 16 + li;
    if (dsth) dsth[oi] = acc;

    float4 o;
    if (mode == 0) {
        float4 x = (r < NU) ? __ldg(&ue[oi])
                            : __ldg(&ie[(size_t)(r - NU) * 16 + li]);
        o = make_float4(x.x + acc.x, x.y + acc.y, x.z + acc.z, x.w + acc.w);
    } else {
        o = out[oi];
        o.x += acc.x; o.y += acc.y; o.z += acc.z; o.w += acc.w;
        if (mode == 2) { o.x *= 0.25f; o.y *= 0.25f; o.z *= 0.25f; o.w *= 0.25f; }
    }
    out[oi] = o;
}

extern "C" void kernel_launch(void* const* d_in, const int* in_sizes, int n_in,
                              void* d_out, int out_size) {
    const float* ue = (const float*)d_in[0];
    const float* ie = (const float*)d_in[1];
    const int*   ei = (const int*)d_in[2];
    const int* row = ei;
    const int* col = ei + NE;
    float4* out = (float4*)d_out;

    const int B = 256;
    const int gN = (NN + B - 1) / B;
    const int gE = (NE + B - 1) / B;
    const int gL = ((NN * 16) + B - 1) / B;

    // CSR build
    k_zero_cnt<<<gN, B>>>();
    k_count<<<gE, B>>>(row);
    k_dinv<<<gN, B>>>();
    k_scan1<<<NBLK, 1024>>>();
    k_scan2<<<1, 512>>>();
    k_scan3<<<gN, B>>>();
    k_fill<<<gE, B>>>(row, col);

    // Layers (fused h-write + out-accumulate)
    k_layer<<<gL, B>>>((const float4*)ue, (const float4*)ie, out, 0);
    k_layer<<<gL, B>>>((const float4*)ue, (const float4*)ie, out, 1);
    k_layer<<<gL, B>>>((const float4*)ue, (const float4*)ie, out, 2);
}

// round 5
// speedup vs baseline: 1.5731x; 1.0836x over previous
#include <cuda_runtime.h>

// LightGCN 3-layer propagation on GB300 (sm_103a) — CSR gather, deferred output.
//   Build CSR (5 kernels), then:
//     layer1: hA[r] = sum norm*x[col]          (x = concat(ue,ie), write hA only)
//     layer2: hB[r] = sum norm*hA[col]         (write hB only)
//     layer3: out[r] = 0.25*(x + hA + hB + sum norm*hB[col])   (single out pass)
// Edge records packed as {col:int, norm:float} for one LDG.64 per edge per lane.

#define NU 200000
#define NI 100000
#define NN 300000
#define DIM 64
#define NE 1200000
#define NBLK ((NN + 1023) / 1024)   // 293 scan blocks

struct Edge { int c; float nm; };

__device__ int   g_cnt[NN];
__device__ int   g_offs[NN];
__device__ int   g_cur[NN];
__device__ int   g_bsum[NBLK];
__device__ float g_dinv[NN];
__device__ Edge  g_edge[NE];
__device__ float g_hA[(size_t)NN * DIM];
__device__ float g_hB[(size_t)NN * DIM];

__global__ void k_zero_cnt() {
    int i = blockIdx.x * blockDim.x + threadIdx.x;
    if (i < NN) g_cnt[i] = 0;
}

__global__ void k_count(const int* __restrict__ row) {
    int e = blockIdx.x * blockDim.x + threadIdx.x;
    if (e < NE) atomicAdd(&g_cnt[row[e]], 1);
}

// Block-level exclusive scan of g_cnt; also computes dinv (degree already in hand).
__global__ void k_scan1() {
    __shared__ int sh[1024];
    int i = blockIdx.x * 1024 + threadIdx.x;
    int v = (i < NN) ? g_cnt[i] : 0;
    if (i < NN) g_dinv[i] = (v > 0) ? rsqrtf((float)v) : 0.0f;
    sh[threadIdx.x] = v;
    __syncthreads();
    for (int off = 1; off < 1024; off <<= 1) {
        int t = (threadIdx.x >= off) ? sh[threadIdx.x - off] : 0;
        __syncthreads();
        sh[threadIdx.x] += t;
        __syncthreads();
    }
    if (i < NN) g_offs[i] = sh[threadIdx.x] - v;
    if (threadIdx.x == 1023) g_bsum[blockIdx.x] = sh[1023];
}

// Each block sums the bsum partials below it (<=293 ints) for its base, then
// finalizes offs and cursors. Replaces a separate scan2+scan3 pair.
__global__ void k_scan2() {
    __shared__ int base_sh;
    int b = blockIdx.x;
    if (threadIdx.x < 32) {
        int s = 0;
        for (int j = threadIdx.x; j < b; j += 32) s += g_bsum[j];
        #pragma unroll
        for (int o = 16; o; o >>= 1) s += __shfl_down_sync(0xffffffffu, s, o);
        if (threadIdx.x == 0) base_sh = s;
    }
    __syncthreads();
    int i = b * 1024 + threadIdx.x;
    if (i < NN) {
        int o = g_offs[i] + base_sh;
        g_offs[i] = o;
        g_cur[i]  = o;
    }
}

__global__ void k_fill(const int* __restrict__ row, const int* __restrict__ col) {
    int e = blockIdx.x * blockDim.x + threadIdx.x;
    if (e < NE) {
        int r = row[e], c = col[e];
        int pos = atomicAdd(&g_cur[r], 1);
        Edge ed;
        ed.c  = c;
        ed.nm = __ldg(&g_dinv[r]) * __ldg(&g_dinv[c]);
        g_edge[pos] = ed;
    }
}

// Gather one row's neighbor sum: 16 lanes per row, one float4 slice per lane.
__device__ __forceinline__ float4 row_gather(
    int r, int li, const float4* __restrict__ ue, const float4* __restrict__ ie,
    const float4* __restrict__ src, int fromEmb)
{
    int start = g_offs[r];
    int cnt   = g_cnt[r];
    float4 acc = make_float4(0.f, 0.f, 0.f, 0.f);
    const int2* __restrict__ ep = reinterpret_cast<const int2*>(g_edge) + start;
    for (int j = 0; j < cnt; j++) {
        int2 e = __ldg(&ep[j]);               // one 64-bit load: {col, norm}
        int   c  = e.x;
        float nm = __int_as_float(e.y);
        float4 v;
        if (fromEmb)
            v = (c < NU) ? __ldg(&ue[(size_t)c * 16 + li])
                         : __ldg(&ie[(size_t)(c - NU) * 16 + li]);
        else
            v = __ldg(&src[(size_t)c * 16 + li]);
        acc.x += nm * v.x; acc.y += nm * v.y;
        acc.z += nm * v.z; acc.w += nm * v.w;
    }
    return acc;
}

// Layer 1: hA = A_norm @ x    (x read directly from embeddings)
__global__ void __launch_bounds__(256) k_layer1(
    const float4* __restrict__ ue, const float4* __restrict__ ie)
{
    int t = blockIdx.x * blockDim.x + threadIdx.x;
    int r = t >> 4;
    if (r >= NN) return;
    int li = t & 15;
    float4 acc = row_gather(r, li, ue, ie, nullptr, 1);
    reinterpret_cast<float4*>(g_hA)[(size_t)r * 16 + li] = acc;
}

// Layer 2: hB = A_norm @ hA
__global__ void __launch_bounds__(256) k_layer2() {
    int t = blockIdx.x * blockDim.x + threadIdx.x;
    int r = t >> 4;
    if (r >= NN) return;
    int li = t & 15;
    float4 acc = row_gather(r, li, nullptr, nullptr, (const float4*)g_hA, 0);
    reinterpret_cast<float4*>(g_hB)[(size_t)r * 16 + li] = acc;
}

// Layer 3: out = 0.25 * (x + hA + hB + A_norm @ hB)
__global__ void __launch_bounds__(256) k_layer3(
    const float4* __restrict__ ue, const float4* __restrict__ ie,
    float4* __restrict__ out)
{
    int t = blockIdx.x * blockDim.x + threadIdx.x;
    int r = t >> 4;
    if (r >= NN) return;
    int li = t & 15;

    float4 h3 = row_gather(r, li, nullptr, nullptr, (const float4*)g_hB, 0);

    size_t oi = (size_t)r * 16 + li;
    float4 x  = (r < NU) ? __ldg(&ue[oi]) : __ldg(&ie[(size_t)(r - NU) * 16 + li]);
    float4 h1 = reinterpret_cast<const float4*>(g_hA)[oi];
    float4 h2 = reinterpret_cast<const float4*>(g_hB)[oi];

    float4 o;
    o.x = 0.25f * (x.x + h1.x + h2.x + h3.x);
    o.y = 0.25f * (x.y + h1.y + h2.y + h3.y);
    o.z = 0.25f * (x.z + h1.z + h2.z + h3.z);
    o.w = 0.25f * (x.w + h1.w + h2.w + h3.w);
    out[oi] = o;
}

extern "C" void kernel_launch(void* const* d_in, const int* in_sizes, int n_in,
                              void* d_out, int out_size) {
    const float* ue = (const float*)d_in[0];
    const float* ie = (const float*)d_in[1];
    const int*   ei = (const int*)d_in[2];
    const int* row = ei;
    const int* col = ei + NE;
    float4* out = (float4*)d_out;

    const int B = 256;
    const int gN = (NN + B - 1) / B;
    const int gE = (NE + B - 1) / B;
    const int gL = ((NN * 16) + B - 1) / B;

    // CSR build (5 launches so that ncu -s 5 captures k_layer1)
    k_zero_cnt<<<gN, B>>>();
    k_count<<<gE, B>>>(row);
    k_scan1<<<NBLK, 1024>>>();
    k_scan2<<<NBLK, 1024>>>();
    k_fill<<<gE, B>>>(row, col);

    // Layers
    k_layer1<<<gL, B>>>((const float4*)ue, (const float4*)ie);
    k_layer2<<<gL, B>>>();
    k_layer3<<<gL, B>>>((const float4*)ue, (const float4*)ie, out);
}